// round 9
// baseline (speedup 1.0000x reference)
#include <cuda_runtime.h>
#include <cuda_bf16.h>

// GraphNorm: out = weight * (x - mean[batch]*mean_scale) / std[batch] + bias
// batch is SORTED (int32 on device; probed) -> segment g = contiguous rows
// [lower_bound(g), lower_bound(g+1)).
//
// One-pass stats via E[x^2]:  var = E[x^2] + m^2 * s * (s - 2)
// Output affine per (segment, col): A = w*rsqrt(var+eps), B = bias - s*m*A.
//
// Memory scheme (locked in since R7; traffic == compulsory ~1.0-1.1 GB):
//   pass-1 loads  ld.global.nc.L2::evict_last.v8   (survive store stream)
//   pass-2 loads  ld.global.nc.L2::evict_first.v8  (consume and release)
//   stores        st.global.cs.v4                  (streaming)
// R8: occupancy is the binding constraint (DRAM% tracks occ across rounds).
// __launch_bounds__(256,6) + A/B kept in smem during pass 2 to hold the
// register peak in pass 1 (~36 live) under the 42-reg target.

#define EPS 1e-6f
#define NUM_SEGMENTS 4096   // fixed by problem setup (G)

__device__ __forceinline__ void ld8_keep(const float* p, float* v) {
    unsigned a0,a1,a2,a3,a4,a5,a6,a7;
    asm("ld.global.nc.L2::evict_last.v8.b32 {%0,%1,%2,%3,%4,%5,%6,%7}, [%8];"
        : "=r"(a0),"=r"(a1),"=r"(a2),"=r"(a3),
          "=r"(a4),"=r"(a5),"=r"(a6),"=r"(a7) : "l"(p));
    v[0]=__uint_as_float(a0); v[1]=__uint_as_float(a1);
    v[2]=__uint_as_float(a2); v[3]=__uint_as_float(a3);
    v[4]=__uint_as_float(a4); v[5]=__uint_as_float(a5);
    v[6]=__uint_as_float(a6); v[7]=__uint_as_float(a7);
}

__device__ __forceinline__ void ld8_done(const float* p, float* v) {
    unsigned a0,a1,a2,a3,a4,a5,a6,a7;
    asm("ld.global.nc.L2::evict_first.v8.b32 {%0,%1,%2,%3,%4,%5,%6,%7}, [%8];"
        : "=r"(a0),"=r"(a1),"=r"(a2),"=r"(a3),
          "=r"(a4),"=r"(a5),"=r"(a6),"=r"(a7) : "l"(p));
    v[0]=__uint_as_float(a0); v[1]=__uint_as_float(a1);
    v[2]=__uint_as_float(a2); v[3]=__uint_as_float(a3);
    v[4]=__uint_as_float(a4); v[5]=__uint_as_float(a5);
    v[6]=__uint_as_float(a6); v[7]=__uint_as_float(a7);
}

__device__ __forceinline__ void st4_stream(float* p, float a, float b, float c, float d) {
    asm volatile("st.global.cs.v4.f32 [%0], {%1,%2,%3,%4};"
                 :: "l"(p), "f"(a), "f"(b), "f"(c), "f"(d));
}

__global__ __launch_bounds__(256, 6) void graphnorm_kernel(
    const float* __restrict__ x,
    const void* __restrict__ batch_raw,
    int n,
    const float* __restrict__ weight,
    const float* __restrict__ bias,
    const float* __restrict__ mean_scale,
    float* __restrict__ out)
{
    const int g = blockIdx.x;
    const int t = threadIdx.x;
    const int o = t & 15;   // octet: owns columns [8o, 8o+8)
    const int r = t >> 4;   // row-lane: strides rows by 16

    __shared__ int sBounds[2];
    __shared__ int sIsI64;
    __shared__ float s_sum[8][128];
    __shared__ float s_sq [8][128];
    __shared__ float sA[128];
    __shared__ float sB[128];

    // Dtype probe (in-bounds either way): largest odd u32 index j:
    // int32 -> value near 4095 (nonzero); int64 -> high word (zero).
    if (t == 0) {
        int j = n - 1;
        if ((j & 1) == 0) j -= 1;
        if (j < 1) j = 1;
        sIsI64 = (((const unsigned*)batch_raw)[j] == 0u) ? 1 : 0;
    }
    __syncthreads();
    const int isI64 = sIsI64;

    // Threads 0 and 1 each run one lower_bound over the sorted batch array.
    if (t < 2) {
        int key = g + t;
        int lo = 0, hi = n;
        if (isI64) {
            const long long* b64 = (const long long*)batch_raw;
            long long k = (long long)key;
            while (lo < hi) {
                int mid = (lo + hi) >> 1;
                if (__ldg(&b64[mid]) < k) lo = mid + 1; else hi = mid;
            }
        } else {
            const int* b32 = (const int*)batch_raw;
            while (lo < hi) {
                int mid = (lo + hi) >> 1;
                if (__ldg(&b32[mid]) < key) lo = mid + 1; else hi = mid;
            }
        }
        sBounds[t] = lo;
    }
    __syncthreads();

    const int s = sBounds[0];
    const int e = sBounds[1];
    if (e <= s) return;   // empty segment (uniform across CTA)

    float sum[8] = {0,0,0,0,0,0,0,0};
    float sq [8] = {0,0,0,0,0,0,0,0};

    // Pass 1: accumulate; tag lines evict_last so they survive until pass 2.
    for (int i = s + r; i < e; i += 16) {
        float v[8];
        ld8_keep(x + (size_t)i * 128 + o * 8, v);
        #pragma unroll
        for (int j = 0; j < 8; j++) {
            sum[j] += v[j];
            sq [j] += v[j] * v[j];
        }
    }

    // Warp-level pre-reduce: lanes 16-31 (row r+1) fold into lanes 0-15.
    #pragma unroll
    for (int j = 0; j < 8; j++) {
        sum[j] += __shfl_down_sync(0xffffffffu, sum[j], 16);
        sq [j] += __shfl_down_sync(0xffffffffu, sq [j], 16);
    }
    const int w = t >> 5;            // warp id = folded row 0..7
    if ((t & 16) == 0) {
        #pragma unroll
        for (int j = 0; j < 8; j++) {
            s_sum[w][o * 8 + j] = sum[j];
            s_sq [w][o * 8 + j] = sq[j];
        }
    }
    __syncthreads();

    // Tree reduce 8 rows -> 1 using 256 threads over 128 cols x 2 halves.
    {
        const int c = t & 127;
        const int h = t >> 7;        // 0 or 1
        s_sum[h][c] += s_sum[h + 4][c];  s_sum[h + 2][c] += s_sum[h + 6][c];
        s_sq [h][c] += s_sq [h + 4][c];  s_sq [h + 2][c] += s_sq [h + 6][c];
        __syncthreads();
        s_sum[h][c] += s_sum[h + 2][c];
        s_sq [h][c] += s_sq [h + 2][c];
        __syncthreads();
        if (h == 0) {
            s_sum[0][c] += s_sum[1][c];
            s_sq [0][c] += s_sq [1][c];
        }
    }
    __syncthreads();

    // One thread per column: affine coefficients A, B into smem.
    if (t < 128) {
        float inv_cnt = 1.f / (float)(e - s);
        float m  = s_sum[0][t] * inv_cnt;
        float ms = mean_scale[t];
        float var = s_sq[0][t] * inv_cnt + m * m * ms * (ms - 2.f);
        float A = weight[t] * rsqrtf(var + EPS);
        sA[t] = A;
        sB[t] = bias[t] - m * ms * A;
    }
    __syncthreads();

    // Pass 2: consume L2-resident lines (evict_first), stream output (.cs).
    // A/B read from smem each iteration (LDS hidden under the global load)
    // to keep register pressure below the 6-CTA/SM ceiling.
    const float* __restrict__ pA = &sA[o * 8];
    const float* __restrict__ pB = &sB[o * 8];
    for (int i = s + r; i < e; i += 16) {
        float v[8];
        ld8_done(x + (size_t)i * 128 + o * 8, v);
        float w0 = v[0] * pA[0] + pB[0];
        float w1 = v[1] * pA[1] + pB[1];
        float w2 = v[2] * pA[2] + pB[2];
        float w3 = v[3] * pA[3] + pB[3];
        float w4 = v[4] * pA[4] + pB[4];
        float w5 = v[5] * pA[5] + pB[5];
        float w6 = v[6] * pA[6] + pB[6];
        float w7 = v[7] * pA[7] + pB[7];
        float* op = out + (size_t)i * 128 + o * 8;
        st4_stream(op,     w0, w1, w2, w3);
        st4_stream(op + 4, w4, w5, w6, w7);
    }
}

extern "C" void kernel_launch(void* const* d_in, const int* in_sizes, int n_in,
                              void* d_out, int out_size) {
    const float* x          = (const float*)d_in[0];
    const void*  batch      = (const void*)d_in[1];
    // d_in[2] = num_segments (device scalar; grid sized by NUM_SEGMENTS)
    const float* weight     = (const float*)d_in[3];
    const float* bias       = (const float*)d_in[4];
    const float* mean_scale = (const float*)d_in[5];
    float*       out        = (float*)d_out;

    const int D = 128;
    const int N = in_sizes[0] / D;

    graphnorm_kernel<<<NUM_SEGMENTS, 256>>>(x, batch, N, weight, bias,
                                            mean_scale, out);
}

// round 10
// speedup vs baseline: 1.0675x; 1.0675x over previous
#include <cuda_runtime.h>
#include <cuda_bf16.h>

// GraphNorm: out = weight * (x - mean[batch]*mean_scale) / std[batch] + bias
// batch is SORTED (int32 on device; probed) -> segment g = contiguous rows
// [lower_bound(g), lower_bound(g+1)).
//
// One-pass stats via E[x^2]:  var = E[x^2] + m^2 * s * (s - 2)
// Output affine per (segment, col): A = w*rsqrt(var+eps), B = bias - s*m*A.
//
// R9 lesson: traffic scales with (concurrent CTAs) x (segment bytes) — the
// inter-pass L2 footprint. 6 small CTAs/SM overflowed the evict_last class
// (111 MB vs 126 MB L2) and thrashed (1.54 GB HBM). BW needs warps; L2 reuse
// needs few concurrent segments. Decouple with BIGGER CTAs:
//   512 thr/CTA, 3 CTAs/SM = 48 warps (75% occ) but only 3 concurrent
//   segments/SM -> footprint ~55 MB << L2. Hints as before:
//   pass-1 ld.v8 evict_last, pass-2 ld.v8 evict_first, st.cs stores.

#define EPS 1e-6f
#define NUM_SEGMENTS 4096   // fixed by problem setup (G)

__device__ __forceinline__ void ld8_keep(const float* p, float* v) {
    unsigned a0,a1,a2,a3,a4,a5,a6,a7;
    asm("ld.global.nc.L2::evict_last.v8.b32 {%0,%1,%2,%3,%4,%5,%6,%7}, [%8];"
        : "=r"(a0),"=r"(a1),"=r"(a2),"=r"(a3),
          "=r"(a4),"=r"(a5),"=r"(a6),"=r"(a7) : "l"(p));
    v[0]=__uint_as_float(a0); v[1]=__uint_as_float(a1);
    v[2]=__uint_as_float(a2); v[3]=__uint_as_float(a3);
    v[4]=__uint_as_float(a4); v[5]=__uint_as_float(a5);
    v[6]=__uint_as_float(a6); v[7]=__uint_as_float(a7);
}

__device__ __forceinline__ void ld8_done(const float* p, float* v) {
    unsigned a0,a1,a2,a3,a4,a5,a6,a7;
    asm("ld.global.nc.L2::evict_first.v8.b32 {%0,%1,%2,%3,%4,%5,%6,%7}, [%8];"
        : "=r"(a0),"=r"(a1),"=r"(a2),"=r"(a3),
          "=r"(a4),"=r"(a5),"=r"(a6),"=r"(a7) : "l"(p));
    v[0]=__uint_as_float(a0); v[1]=__uint_as_float(a1);
    v[2]=__uint_as_float(a2); v[3]=__uint_as_float(a3);
    v[4]=__uint_as_float(a4); v[5]=__uint_as_float(a5);
    v[6]=__uint_as_float(a6); v[7]=__uint_as_float(a7);
}

__device__ __forceinline__ void st4_stream(float* p, float a, float b, float c, float d) {
    asm volatile("st.global.cs.v4.f32 [%0], {%1,%2,%3,%4};"
                 :: "l"(p), "f"(a), "f"(b), "f"(c), "f"(d));
}

__global__ __launch_bounds__(512, 3) void graphnorm_kernel(
    const float* __restrict__ x,
    const void* __restrict__ batch_raw,
    int n,
    const float* __restrict__ weight,
    const float* __restrict__ bias,
    const float* __restrict__ mean_scale,
    float* __restrict__ out)
{
    const int g = blockIdx.x;
    const int t = threadIdx.x;
    const int o = t & 15;   // octet: owns columns [8o, 8o+8)
    const int r = t >> 4;   // row-lane 0..31: strides rows by 32

    __shared__ int sBounds[2];
    __shared__ int sIsI64;
    __shared__ float s_sum[16][128];
    __shared__ float s_sq [16][128];
    __shared__ float sA[128];
    __shared__ float sB[128];

    // Dtype probe (in-bounds either way): largest odd u32 index j:
    // int32 -> value near 4095 (nonzero); int64 -> high word (zero).
    if (t == 0) {
        int j = n - 1;
        if ((j & 1) == 0) j -= 1;
        if (j < 1) j = 1;
        sIsI64 = (((const unsigned*)batch_raw)[j] == 0u) ? 1 : 0;
    }
    __syncthreads();
    const int isI64 = sIsI64;

    // Threads 0 and 1 each run one lower_bound over the sorted batch array.
    if (t < 2) {
        int key = g + t;
        int lo = 0, hi = n;
        if (isI64) {
            const long long* b64 = (const long long*)batch_raw;
            long long k = (long long)key;
            while (lo < hi) {
                int mid = (lo + hi) >> 1;
                if (__ldg(&b64[mid]) < k) lo = mid + 1; else hi = mid;
            }
        } else {
            const int* b32 = (const int*)batch_raw;
            while (lo < hi) {
                int mid = (lo + hi) >> 1;
                if (__ldg(&b32[mid]) < key) lo = mid + 1; else hi = mid;
            }
        }
        sBounds[t] = lo;
    }
    __syncthreads();

    const int s = sBounds[0];
    const int e = sBounds[1];
    if (e <= s) return;   // empty segment (uniform across CTA)

    float sum[8] = {0,0,0,0,0,0,0,0};
    float sq [8] = {0,0,0,0,0,0,0,0};

    // Pass 1: accumulate; tag lines evict_last so they survive until pass 2.
    for (int i = s + r; i < e; i += 32) {
        float v[8];
        ld8_keep(x + (size_t)i * 128 + o * 8, v);
        #pragma unroll
        for (int j = 0; j < 8; j++) {
            sum[j] += v[j];
            sq [j] += v[j] * v[j];
        }
    }

    // Warp-level pre-reduce: lanes 16-31 fold into lanes 0-15 (32 rows -> 16).
    #pragma unroll
    for (int j = 0; j < 8; j++) {
        sum[j] += __shfl_down_sync(0xffffffffu, sum[j], 16);
        sq [j] += __shfl_down_sync(0xffffffffu, sq [j], 16);
    }
    const int w = t >> 5;            // warp id 0..15 = folded row
    if ((t & 16) == 0) {
        #pragma unroll
        for (int j = 0; j < 8; j++) {
            s_sum[w][o * 8 + j] = sum[j];
            s_sq [w][o * 8 + j] = sq[j];
        }
    }
    __syncthreads();

    // Tree reduce 16 rows -> 1 with 512 threads = 4 groups x 128 cols.
    {
        const int c = t & 127;
        const int h = t >> 7;        // 0..3
        // 16 -> 8
        s_sum[h][c] += s_sum[h + 8][c];   s_sum[h + 4][c] += s_sum[h + 12][c];
        s_sq [h][c] += s_sq [h + 8][c];   s_sq [h + 4][c] += s_sq [h + 12][c];
        __syncthreads();
        // 8 -> 4
        s_sum[h][c] += s_sum[h + 4][c];
        s_sq [h][c] += s_sq [h + 4][c];
        __syncthreads();
        // 4 -> 2
        if (h < 2) {
            s_sum[h][c] += s_sum[h + 2][c];
            s_sq [h][c] += s_sq [h + 2][c];
        }
        __syncthreads();
        // 2 -> 1
        if (h == 0) {
            s_sum[0][c] += s_sum[1][c];
            s_sq [0][c] += s_sq [1][c];
        }
    }
    __syncthreads();

    // One thread per column: affine coefficients A, B into smem.
    if (t < 128) {
        float inv_cnt = 1.f / (float)(e - s);
        float m  = s_sum[0][t] * inv_cnt;
        float ms = mean_scale[t];
        float var = s_sq[0][t] * inv_cnt + m * m * ms * (ms - 2.f);
        float A = weight[t] * rsqrtf(var + EPS);
        sA[t] = A;
        sB[t] = bias[t] - m * ms * A;
    }
    __syncthreads();

    // Pass 2: consume L2-resident lines (evict_first), stream output (.cs).
    // A/B read from smem (LDS hidden under global loads; keeps regs low).
    const float* __restrict__ pA = &sA[o * 8];
    const float* __restrict__ pB = &sB[o * 8];
    for (int i = s + r; i < e; i += 32) {
        float v[8];
        ld8_done(x + (size_t)i * 128 + o * 8, v);
        float w0 = v[0] * pA[0] + pB[0];
        float w1 = v[1] * pA[1] + pB[1];
        float w2 = v[2] * pA[2] + pB[2];
        float w3 = v[3] * pA[3] + pB[3];
        float w4 = v[4] * pA[4] + pB[4];
        float w5 = v[5] * pA[5] + pB[5];
        float w6 = v[6] * pA[6] + pB[6];
        float w7 = v[7] * pA[7] + pB[7];
        float* op = out + (size_t)i * 128 + o * 8;
        st4_stream(op,     w0, w1, w2, w3);
        st4_stream(op + 4, w4, w5, w6, w7);
    }
}

extern "C" void kernel_launch(void* const* d_in, const int* in_sizes, int n_in,
                              void* d_out, int out_size) {
    const float* x          = (const float*)d_in[0];
    const void*  batch      = (const void*)d_in[1];
    // d_in[2] = num_segments (device scalar; grid sized by NUM_SEGMENTS)
    const float* weight     = (const float*)d_in[3];
    const float* bias       = (const float*)d_in[4];
    const float* mean_scale = (const float*)d_in[5];
    float*       out        = (float*)d_out;

    const int D = 128;
    const int N = in_sizes[0] / D;

    graphnorm_kernel<<<NUM_SEGMENTS, 512>>>(x, batch, N, weight, bias,
                                            mean_scale, out);
}

// round 11
// speedup vs baseline: 1.1982x; 1.1224x over previous
#include <cuda_runtime.h>
#include <cuda_bf16.h>

// GraphNorm: out = weight * (x - mean[batch]*mean_scale) / std[batch] + bias
// batch is SORTED (int32 on device; probed) -> segment g = contiguous rows
// [lower_bound(g), lower_bound(g+1)).
//
// One-pass stats via E[x^2]:  var = E[x^2] + m^2 * s * (s - 2)
// Output affine per (segment, col): A = w*rsqrt(var+eps), B = bias - s*m*A.
//
// Design point (from R5-R10 sweep):
//   - BW tracks warps/SM, and small CTAs beat big CTAs at equal warps
//     (512-thr CTAs couple 16 warps per barrier -> R10 BW regression).
//   - Traffic blows up when (concurrent segments) x (segment bytes) exceeds
//     the L2 evict_last capacity (R9: 111 MB -> thrash, 1.54 GB).
//   - Fix: hybrid smem cache. 256 thr x 6 CTAs/SM (48 warps), each CTA
//     caches the first 54 rows (27 KB) of its segment in smem during
//     pass 1; pass-2 L2 footprint drops to ~85 MB < 126 MB.
// Hints: pass-1 ld.v8 evict_last, pass-2 ld.v8 evict_first, st.cs stores.

#define EPS 1e-6f
#define NUM_SEGMENTS 4096   // fixed by problem setup (G)
#define CACHE_ROWS 54       // 54 * 512 B = 27 KB smem row cache per CTA

__device__ __forceinline__ void ld8_keep(const float* p, float* v) {
    unsigned a0,a1,a2,a3,a4,a5,a6,a7;
    asm("ld.global.nc.L2::evict_last.v8.b32 {%0,%1,%2,%3,%4,%5,%6,%7}, [%8];"
        : "=r"(a0),"=r"(a1),"=r"(a2),"=r"(a3),
          "=r"(a4),"=r"(a5),"=r"(a6),"=r"(a7) : "l"(p));
    v[0]=__uint_as_float(a0); v[1]=__uint_as_float(a1);
    v[2]=__uint_as_float(a2); v[3]=__uint_as_float(a3);
    v[4]=__uint_as_float(a4); v[5]=__uint_as_float(a5);
    v[6]=__uint_as_float(a6); v[7]=__uint_as_float(a7);
}

__device__ __forceinline__ void ld8_done(const float* p, float* v) {
    unsigned a0,a1,a2,a3,a4,a5,a6,a7;
    asm("ld.global.nc.L2::evict_first.v8.b32 {%0,%1,%2,%3,%4,%5,%6,%7}, [%8];"
        : "=r"(a0),"=r"(a1),"=r"(a2),"=r"(a3),
          "=r"(a4),"=r"(a5),"=r"(a6),"=r"(a7) : "l"(p));
    v[0]=__uint_as_float(a0); v[1]=__uint_as_float(a1);
    v[2]=__uint_as_float(a2); v[3]=__uint_as_float(a3);
    v[4]=__uint_as_float(a4); v[5]=__uint_as_float(a5);
    v[6]=__uint_as_float(a6); v[7]=__uint_as_float(a7);
}

__device__ __forceinline__ void st4_stream(float* p, float a, float b, float c, float d) {
    asm volatile("st.global.cs.v4.f32 [%0], {%1,%2,%3,%4};"
                 :: "l"(p), "f"(a), "f"(b), "f"(c), "f"(d));
}

__global__ __launch_bounds__(256, 6) void graphnorm_kernel(
    const float* __restrict__ x,
    const void* __restrict__ batch_raw,
    int n,
    const float* __restrict__ weight,
    const float* __restrict__ bias,
    const float* __restrict__ mean_scale,
    float* __restrict__ out)
{
    const int g = blockIdx.x;
    const int t = threadIdx.x;
    const int o = t & 15;   // octet: owns columns [8o, 8o+8)
    const int r = t >> 4;   // row-lane 0..15: strides rows by 16

    __shared__ int sBounds[2];
    __shared__ int sIsI64;
    __shared__ float s_sum[8][128];
    __shared__ float s_sq [8][128];
    __shared__ float sA[128];
    __shared__ float sB[128];
    __shared__ __align__(16) float s_cache[CACHE_ROWS][128];  // 27 KB

    // Dtype probe (in-bounds either way): largest odd u32 index j:
    // int32 -> value near 4095 (nonzero); int64 -> high word (zero).
    if (t == 0) {
        int j = n - 1;
        if ((j & 1) == 0) j -= 1;
        if (j < 1) j = 1;
        sIsI64 = (((const unsigned*)batch_raw)[j] == 0u) ? 1 : 0;
    }
    __syncthreads();
    const int isI64 = sIsI64;

    // Threads 0 and 1 each run one lower_bound over the sorted batch array.
    if (t < 2) {
        int key = g + t;
        int lo = 0, hi = n;
        if (isI64) {
            const long long* b64 = (const long long*)batch_raw;
            long long k = (long long)key;
            while (lo < hi) {
                int mid = (lo + hi) >> 1;
                if (__ldg(&b64[mid]) < k) lo = mid + 1; else hi = mid;
            }
        } else {
            const int* b32 = (const int*)batch_raw;
            while (lo < hi) {
                int mid = (lo + hi) >> 1;
                if (__ldg(&b32[mid]) < key) lo = mid + 1; else hi = mid;
            }
        }
        sBounds[t] = lo;
    }
    __syncthreads();

    const int s = sBounds[0];
    const int e = sBounds[1];
    if (e <= s) return;   // empty segment (uniform across CTA)

    float sum[8] = {0,0,0,0,0,0,0,0};
    float sq [8] = {0,0,0,0,0,0,0,0};

    // Pass 1: accumulate; stash early rows in smem; tag the rest evict_last.
    for (int i = s + r; i < e; i += 16) {
        float v[8];
        ld8_keep(x + (size_t)i * 128 + o * 8, v);
        const int ci = i - s;
        if (ci < CACHE_ROWS) {
            float4* cp = (float4*)&s_cache[ci][o * 8];
            cp[0] = make_float4(v[0], v[1], v[2], v[3]);
            cp[1] = make_float4(v[4], v[5], v[6], v[7]);
        }
        #pragma unroll
        for (int j = 0; j < 8; j++) {
            sum[j] += v[j];
            sq [j] += v[j] * v[j];
        }
    }

    // Warp-level pre-reduce: lanes 16-31 (row r+1) fold into lanes 0-15.
    #pragma unroll
    for (int j = 0; j < 8; j++) {
        sum[j] += __shfl_down_sync(0xffffffffu, sum[j], 16);
        sq [j] += __shfl_down_sync(0xffffffffu, sq [j], 16);
    }
    const int w = t >> 5;            // warp id = folded row 0..7
    if ((t & 16) == 0) {
        #pragma unroll
        for (int j = 0; j < 8; j++) {
            s_sum[w][o * 8 + j] = sum[j];
            s_sq [w][o * 8 + j] = sq[j];
        }
    }
    __syncthreads();

    // Tree reduce 8 rows -> 1 using 256 threads over 128 cols x 2 halves.
    {
        const int c = t & 127;
        const int h = t >> 7;        // 0 or 1
        s_sum[h][c] += s_sum[h + 4][c];  s_sum[h + 2][c] += s_sum[h + 6][c];
        s_sq [h][c] += s_sq [h + 4][c];  s_sq [h + 2][c] += s_sq [h + 6][c];
        __syncthreads();
        s_sum[h][c] += s_sum[h + 2][c];
        s_sq [h][c] += s_sq [h + 2][c];
        __syncthreads();
        if (h == 0) {
            s_sum[0][c] += s_sum[1][c];
            s_sq [0][c] += s_sq [1][c];
        }
    }
    __syncthreads();

    // One thread per column: affine coefficients A, B into smem.
    if (t < 128) {
        float inv_cnt = 1.f / (float)(e - s);
        float m  = s_sum[0][t] * inv_cnt;
        float ms = mean_scale[t];
        float var = s_sq[0][t] * inv_cnt + m * m * ms * (ms - 2.f);
        float A = weight[t] * rsqrtf(var + EPS);
        sA[t] = A;
        sB[t] = bias[t] - m * ms * A;
    }
    __syncthreads();

    // Pass 2: cached rows from smem; remainder from L2 (evict_first);
    // stream output (.cs). A/B from smem keeps register pressure low.
    const float* __restrict__ pA = &sA[o * 8];
    const float* __restrict__ pB = &sB[o * 8];
    for (int i = s + r; i < e; i += 16) {
        float v[8];
        const int ci = i - s;
        if (ci < CACHE_ROWS) {
            const float4* cp = (const float4*)&s_cache[ci][o * 8];
            float4 a = cp[0], b = cp[1];
            v[0]=a.x; v[1]=a.y; v[2]=a.z; v[3]=a.w;
            v[4]=b.x; v[5]=b.y; v[6]=b.z; v[7]=b.w;
        } else {
            ld8_done(x + (size_t)i * 128 + o * 8, v);
        }
        float w0 = v[0] * pA[0] + pB[0];
        float w1 = v[1] * pA[1] + pB[1];
        float w2 = v[2] * pA[2] + pB[2];
        float w3 = v[3] * pA[3] + pB[3];
        float w4 = v[4] * pA[4] + pB[4];
        float w5 = v[5] * pA[5] + pB[5];
        float w6 = v[6] * pA[6] + pB[6];
        float w7 = v[7] * pA[7] + pB[7];
        float* op = out + (size_t)i * 128 + o * 8;
        st4_stream(op,     w0, w1, w2, w3);
        st4_stream(op + 4, w4, w5, w6, w7);
    }
}

extern "C" void kernel_launch(void* const* d_in, const int* in_sizes, int n_in,
                              void* d_out, int out_size) {
    const float* x          = (const float*)d_in[0];
    const void*  batch      = (const void*)d_in[1];
    // d_in[2] = num_segments (device scalar; grid sized by NUM_SEGMENTS)
    const float* weight     = (const float*)d_in[3];
    const float* bias       = (const float*)d_in[4];
    const float* mean_scale = (const float*)d_in[5];
    float*       out        = (float*)d_out;

    const int D = 128;
    const int N = in_sizes[0] / D;

    graphnorm_kernel<<<NUM_SEGMENTS, 256>>>(x, batch, N, weight, bias,
                                            mean_scale, out);
}